// round 5
// baseline (speedup 1.0000x reference)
#include <cuda_runtime.h>

// ---------------------------------------------------------------------------
// LQActiv (2-bit learned quantization), Q_T = 1 — single fused kernel.
//
// Algebraic form: levels {±(B1±B0)}, B1=max|basis|, B0=min|basis|,
// thresholds {-B1, 0, +B1}:
//     q  = (|w| > B1) ? +1 : -1
//     wq = copysign(fma(q, B0, B1), w)
// Sufficient statistics: Sabs=Σ|w|, Sqw=Σq|w|, Sq=Σq (signs/order fixed in
// the final 2x2 solve).
//
// Grid = exactly one resident wave (6 blocks/SM @ 40 regs, 148 SMs = 888
// blocks) to avoid wave-quantization. Per-block partials go to plain global
// slots (no atomic contention); an atomic ticket elects the last block, which
// reduces the 888 partials, handles the scalar tail, solves, writes
// out[n..n+2), and resets the ticket for graph replay.
// ---------------------------------------------------------------------------

#define LQ_BLOCKS  888
#define LQ_THREADS 256

__device__ double       g_pabs[LQ_BLOCKS];
__device__ double       g_pqw [LQ_BLOCKS];
__device__ double       g_pq  [LQ_BLOCKS];
__device__ unsigned int g_count;

__device__ __forceinline__ float lq_step(float w, float B0, float B1,
                                         float& sabs, float& sqw, float& sq) {
    float aw = fabsf(w);
    float qf = (aw > B1) ? 1.0f : -1.0f;
    float qv = copysignf(fmaf(qf, B0, B1), w);
    sabs += aw;                 // FADD with |.| modifier
    sqw   = fmaf(qf, aw, sqw);  // FFMA
    sq   += qf;                 // FADD (exact small ints in fp32)
    return qv;
}

__device__ __forceinline__ float4 lq_step4(float4 v, float B0, float B1,
                                           float& sabs, float& sqw, float& sq) {
    float4 o;
    o.x = lq_step(v.x, B0, B1, sabs, sqw, sq);
    o.y = lq_step(v.y, B0, B1, sabs, sqw, sq);
    o.z = lq_step(v.z, B0, B1, sabs, sqw, sq);
    o.w = lq_step(v.w, B0, B1, sabs, sqw, sq);
    return o;
}

__global__ void __launch_bounds__(LQ_THREADS)
lq_fused_kernel(const float* __restrict__ x,
                const float* __restrict__ basis,
                float* __restrict__ out, int n) {
    const float b0 = __ldg(&basis[0]);
    const float b1 = __ldg(&basis[1]);
    const float a0 = fabsf(b0), a1 = fabsf(b1);
    const float B1 = fmaxf(a0, a1);
    const float B0 = fminf(a0, a1);

    const float4* __restrict__ x4   = (const float4*)x;
    float4* __restrict__       out4 = (float4*)out;
    const int n4 = n >> 2;

    float sabs = 0.f, sqw = 0.f, sq = 0.f;

    const int stride = gridDim.x * blockDim.x;
    int i = blockIdx.x * blockDim.x + threadIdx.x;

    // 4-deep batched grid-stride loop: 4 loads in flight, then compute+store.
    for (; i + 3 * stride < n4; i += 4 * stride) {
        float4 v0 = __ldcs(&x4[i]);
        float4 v1 = __ldcs(&x4[i + stride]);
        float4 v2 = __ldcs(&x4[i + 2 * stride]);
        float4 v3 = __ldcs(&x4[i + 3 * stride]);
        float4 q0 = lq_step4(v0, B0, B1, sabs, sqw, sq);
        float4 q1 = lq_step4(v1, B0, B1, sabs, sqw, sq);
        float4 q2 = lq_step4(v2, B0, B1, sabs, sqw, sq);
        float4 q3 = lq_step4(v3, B0, B1, sabs, sqw, sq);
        __stcs(&out4[i], q0);
        __stcs(&out4[i + stride], q1);
        __stcs(&out4[i + 2 * stride], q2);
        __stcs(&out4[i + 3 * stride], q3);
    }
    for (; i < n4; i += stride) {
        float4 v = __ldcs(&x4[i]);
        float4 q = lq_step4(v, B0, B1, sabs, sqw, sq);
        __stcs(&out4[i], q);
    }

    // ---- block reduction: warp shuffle (fp64), shared, then ONE store/block
    double d0 = (double)sabs;
    double d1 = (double)sqw;
    double d2 = (double)sq;

#pragma unroll
    for (int o = 16; o > 0; o >>= 1) {
        d0 += __shfl_down_sync(0xFFFFFFFFu, d0, o);
        d1 += __shfl_down_sync(0xFFFFFFFFu, d1, o);
        d2 += __shfl_down_sync(0xFFFFFFFFu, d2, o);
    }

    __shared__ double sh0[8], sh1[8], sh2[8];
    __shared__ bool   is_last;

    int lane = threadIdx.x & 31;
    int warp = threadIdx.x >> 5;
    if (lane == 0) { sh0[warp] = d0; sh1[warp] = d1; sh2[warp] = d2; }
    __syncthreads();

    if (warp == 0) {
        d0 = (lane < 8) ? sh0[lane] : 0.0;
        d1 = (lane < 8) ? sh1[lane] : 0.0;
        d2 = (lane < 8) ? sh2[lane] : 0.0;
#pragma unroll
        for (int o = 4; o > 0; o >>= 1) {
            d0 += __shfl_down_sync(0xFFFFFFFFu, d0, o);
            d1 += __shfl_down_sync(0xFFFFFFFFu, d1, o);
            d2 += __shfl_down_sync(0xFFFFFFFFu, d2, o);
        }
        if (lane == 0) {
            g_pabs[blockIdx.x] = d0;
            g_pqw [blockIdx.x] = d1;
            g_pq  [blockIdx.x] = d2;
            __threadfence();
            unsigned int ticket = atomicAdd(&g_count, 1u);
            is_last = (ticket == gridDim.x - 1);
        }
    }
    __syncthreads();

    if (!is_last) return;

    // ---- last block: reduce all partials with 256 threads
    double t0 = 0.0, t1 = 0.0, t2 = 0.0;
    for (int k = threadIdx.x; k < (int)gridDim.x; k += blockDim.x) {
        t0 += g_pabs[k];
        t1 += g_pqw [k];
        t2 += g_pq  [k];
    }
#pragma unroll
    for (int o = 16; o > 0; o >>= 1) {
        t0 += __shfl_down_sync(0xFFFFFFFFu, t0, o);
        t1 += __shfl_down_sync(0xFFFFFFFFu, t1, o);
        t2 += __shfl_down_sync(0xFFFFFFFFu, t2, o);
    }
    __syncthreads();  // reuse sh0..sh2 safely
    if (lane == 0) { sh0[warp] = t0; sh1[warp] = t1; sh2[warp] = t2; }
    __syncthreads();

    if (threadIdx.x == 0) {
        double tabs = 0.0, tqw = 0.0, tq = 0.0;
        for (int wI = 0; wI < 8; wI++) {
            tabs += sh0[wI];
            tqw  += sh1[wI];
            tq   += sh2[wI];
        }

        // scalar tail (n % 4)
        int tail = n & 3;
        for (int k = n - tail; k < n; k++) {
            float p0 = 0.f, p1 = 0.f, p2 = 0.f;
            out[k] = lq_step(x[k], B0, B1, p0, p1, p2);
            tabs += (double)p0;
            tqw  += (double)p1;
            tq   += (double)p2;
        }

        // Map (big/small) statistics back to basis index order.
        int big = (a1 >= a0) ? 1 : 0;
        float bbig   = big ? b1 : b0;
        float bsmall = big ? b0 : b1;
        double sgb = (bbig   >= 0.f) ? 1.0 : -1.0;
        double sgs = (bsmall >= 0.f) ? 1.0 : -1.0;

        double bB = sgb * tabs;        // Σ e_big   * w
        double bS = sgs * tqw;         // Σ e_small * w
        double S  = sgb * sgs * tq;    // Σ e0 * e1
        double N  = (double)n;

        double det    = N * N - S * S;
        double vbig   = (N * bB - S * bS) / det;
        double vsmall = (N * bS - S * bB) / det;

        double v0 = big ? vsmall : vbig;
        double v1 = big ? vbig : vsmall;

        out[n]     = 0.9f * b0 + 0.1f * (float)v0;
        out[n + 1] = 0.9f * b1 + 0.1f * (float)v1;

        // Reset ticket for next graph replay (partials are overwritten).
        g_count = 0;
        __threadfence();
    }
}

extern "C" void kernel_launch(void* const* d_in, const int* in_sizes, int n_in,
                              void* d_out, int out_size) {
    int xi = 0, bi = 1;
    if (n_in >= 2 && in_sizes[0] == 2 && in_sizes[1] != 2) { xi = 1; bi = 0; }

    const float* x     = (const float*)d_in[xi];
    const float* basis = (const float*)d_in[bi];
    float* out         = (float*)d_out;

    int n = in_sizes[xi];

    // Exactly one resident wave: 6 blocks/SM (40 regs @ 256 thr) x 148 SMs.
    lq_fused_kernel<<<LQ_BLOCKS, LQ_THREADS>>>(x, basis, out, n);
}